// round 8
// baseline (speedup 1.0000x reference)
#include <cuda_runtime.h>
#include <cuda_fp16.h>
#include <cstdint>

// Problem constants
#define T_TOK 8192
#define DDIM  1024
#define NEXP  8
#define FDIM  2048

// GEMM tiling
#define BM 128
#define BN 64      // gemm1 N tile
#define BN2 128    // gemm2 N tile
#define BK 32
#define LDA 40     // padded A smem stride (halves)
#define LDB 72     // padded B smem stride, gemm1 (halves)
#define LDB2 136   // padded B smem stride, gemm2 (halves)

// Dynamic smem layouts (bytes)
#define ASZ  10240u              // one A stage: 128*40*2
#define BSZ  4608u               // one gemm1 B stage: 32*72*2
#define BSZ2 8704u               // one gemm2 B stage: 32*136*2
#define SM1_B1 30720u            // 3*ASZ
#define SM1_B3 44544u            // 3*ASZ + 3*BSZ
#define SMEM1 58368              // 3*(ASZ+2*BSZ)
#define SM2_B  30720u
#define SMEM2 56832              // 3*(ASZ+BSZ2)

// ---------------------------------------------------------------------------
// Scratch (device globals)
// ---------------------------------------------------------------------------
__device__ __half g_x16[T_TOK * DDIM];
__device__ __half g_w1h[NEXP * DDIM * FDIM];
__device__ __half g_w3h[NEXP * DDIM * FDIM];
__device__ __half g_w2h[NEXP * FDIM * DDIM];
__device__ __half g_h  [T_TOK * 2 * FDIM];   // per-slot hidden activations
__device__ float  g_y  [T_TOK * 2 * DDIM];   // per-slot expert outputs
__device__ int    g_tok[NEXP * T_TOK];       // slot -> token
__device__ int    g_cnt[NEXP];
__device__ int    g_off[NEXP];
__device__ int    g_sel[T_TOK * 2];
__device__ int    g_pos[T_TOK * 2];
__device__ float  g_pk [T_TOK * 2];

// ---------------------------------------------------------------------------
// PTX helpers
// ---------------------------------------------------------------------------
__device__ __forceinline__ uint32_t smem_u32(const void* p) {
    uint32_t a;
    asm("{ .reg .u64 t; cvta.to.shared.u64 t, %1; cvt.u32.u64 %0, t; }"
        : "=r"(a) : "l"(p));
    return a;
}
__device__ __forceinline__ void cp16(uint32_t dst, const void* src, int srcsize) {
    asm volatile("cp.async.cg.shared.global [%0], [%1], 16, %2;\n"
                 :: "r"(dst), "l"(src), "r"(srcsize));
}
__device__ __forceinline__ void cp_commit() {
    asm volatile("cp.async.commit_group;\n");
}
template <int N>
__device__ __forceinline__ void cp_wait() {
    asm volatile("cp.async.wait_group %0;\n" :: "n"(N));
}
__device__ __forceinline__ void ldmx4(uint32_t* r, uint32_t addr) {
    asm volatile("ldmatrix.sync.aligned.m8n8.x4.shared.b16 {%0,%1,%2,%3}, [%4];\n"
                 : "=r"(r[0]), "=r"(r[1]), "=r"(r[2]), "=r"(r[3]) : "r"(addr));
}
__device__ __forceinline__ void ldmx4t(uint32_t* r, uint32_t addr) {
    asm volatile("ldmatrix.sync.aligned.m8n8.x4.trans.shared.b16 {%0,%1,%2,%3}, [%4];\n"
                 : "=r"(r[0]), "=r"(r[1]), "=r"(r[2]), "=r"(r[3]) : "r"(addr));
}
__device__ __forceinline__ void mma16816(float* c, const uint32_t* a, uint32_t b0, uint32_t b1) {
    asm volatile(
        "mma.sync.aligned.m16n8k16.row.col.f32.f16.f16.f32 "
        "{%0,%1,%2,%3}, {%4,%5,%6,%7}, {%8,%9}, {%0,%1,%2,%3};\n"
        : "+f"(c[0]), "+f"(c[1]), "+f"(c[2]), "+f"(c[3])
        : "r"(a[0]), "r"(a[1]), "r"(a[2]), "r"(a[3]), "r"(b0), "r"(b1));
}

// ---------------------------------------------------------------------------
// Kernel 0: zero routing counters
// ---------------------------------------------------------------------------
__global__ void zero_cnt_kernel() {
    if (threadIdx.x < NEXP) g_cnt[threadIdx.x] = 0;
}

// ---------------------------------------------------------------------------
// Kernel 1: fp32 -> fp16 conversion of w1, w3, w2 (vectorized)
// ---------------------------------------------------------------------------
__global__ void convert_kernel(const float* __restrict__ w1,
                               const float* __restrict__ w3,
                               const float* __restrict__ w2) {
    const int n4w = NEXP * DDIM * FDIM / 4;
    for (int i = blockIdx.x * blockDim.x + threadIdx.x; i < n4w;
         i += gridDim.x * blockDim.x) {
        float4 a;
        a = ((const float4*)w1)[i];
        ((__half2*)g_w1h)[2 * i]     = __floats2half2_rn(a.x, a.y);
        ((__half2*)g_w1h)[2 * i + 1] = __floats2half2_rn(a.z, a.w);
        a = ((const float4*)w3)[i];
        ((__half2*)g_w3h)[2 * i]     = __floats2half2_rn(a.x, a.y);
        ((__half2*)g_w3h)[2 * i + 1] = __floats2half2_rn(a.z, a.w);
        a = ((const float4*)w2)[i];
        ((__half2*)g_w2h)[2 * i]     = __floats2half2_rn(a.x, a.y);
        ((__half2*)g_w2h)[2 * i + 1] = __floats2half2_rn(a.z, a.w);
    }
}

// ---------------------------------------------------------------------------
// Kernel 2: gating (exact fp32) + routing + x -> fp16. One warp per token.
// ---------------------------------------------------------------------------
__global__ void gate_kernel(const float* __restrict__ x, const float* __restrict__ wg) {
    int t = blockIdx.x * 8 + (threadIdx.x >> 5);
    int lane = threadIdx.x & 31;
    const float* xr = x + (size_t)t * DDIM;
    float acc[NEXP];
#pragma unroll
    for (int e = 0; e < NEXP; e++) acc[e] = 0.f;
    for (int d = lane; d < DDIM; d += 32) {
        float xv = xr[d];
        g_x16[(size_t)t * DDIM + d] = __float2half(xv);
        const float* wr = wg + d * NEXP;
#pragma unroll
        for (int e = 0; e < NEXP; e++) acc[e] += xv * wr[e];
    }
#pragma unroll
    for (int e = 0; e < NEXP; e++) {
#pragma unroll
        for (int o = 16; o; o >>= 1)
            acc[e] += __shfl_xor_sync(0xffffffffu, acc[e], o);
    }
    if (lane == 0) {
        int e0 = 0; float b0 = acc[0];
#pragma unroll
        for (int e = 1; e < NEXP; e++)
            if (acc[e] > b0) { b0 = acc[e]; e0 = e; }   // strict >: lowest index on tie
        int e1 = -1; float b1 = -1e30f;
#pragma unroll
        for (int e = 0; e < NEXP; e++)
            if (e != e0 && acc[e] > b1) { b1 = acc[e]; e1 = e; }
        float ex  = expf(b1 - b0);
        float inv = 1.f / (1.f + ex);
        int pos0 = atomicAdd(&g_cnt[e0], 1);
        int pos1 = atomicAdd(&g_cnt[e1], 1);
        g_tok[e0 * T_TOK + pos0] = t;
        g_tok[e1 * T_TOK + pos1] = t;
        g_sel[2 * t] = e0;   g_sel[2 * t + 1] = e1;
        g_pos[2 * t] = pos0; g_pos[2 * t + 1] = pos1;
        g_pk [2 * t] = inv;  g_pk [2 * t + 1] = ex * inv;
    }
}

// ---------------------------------------------------------------------------
// Kernel 3: exclusive prefix sum over 8 counters
// ---------------------------------------------------------------------------
__global__ void offsets_kernel() {
    if (threadIdx.x == 0) {
        int run = 0;
        for (int e = 0; e < NEXP; e++) { g_off[e] = run; run += g_cnt[e]; }
    }
}

// ---------------------------------------------------------------------------
// Kernel 4: grouped GEMM1 — h = silu(x@w1) * (x@w3), gathered rows.
// BM=128, BN=64 (dual B), BK=32, 3-stage cp.async, 1 sync/iter.
// 8 warps (4 M x 2 N), warp tile 32x32 per matrix.
// ---------------------------------------------------------------------------
__global__ __launch_bounds__(256, 2) void gemm1_kernel() {
    const int e  = blockIdx.z;
    const int ne = g_cnt[e];
    const int m0 = blockIdx.y * BM;
    if (m0 >= ne) return;
    const int n0 = blockIdx.x * BN;

    __shared__ int stok[BM];
    extern __shared__ __half sm1[];
    const uint32_t sa  = smem_u32(sm1);
    const uint32_t sb1 = sa + SM1_B1;
    const uint32_t sb3 = sa + SM1_B3;

    const int tid = threadIdx.x, lane = tid & 31, warp = tid >> 5;
    const int wm = warp & 3, wn = warp >> 2;

    if (tid < BM) {
        int r = m0 + tid;
        stok[tid] = (r < ne) ? g_tok[e * T_TOK + r] : -1;
    }
    __syncthreads();

    const __half* w1p = g_w1h + (size_t)e * DDIM * FDIM;
    const __half* w3p = g_w3h + (size_t)e * DDIM * FDIM;

    float acc1[2][4][4], acc3[2][4][4];
#pragma unroll
    for (int i = 0; i < 2; i++)
#pragma unroll
        for (int j = 0; j < 4; j++)
#pragma unroll
            for (int q = 0; q < 4; q++) { acc1[i][j][q] = 0.f; acc3[i][j][q] = 0.f; }

    auto load_stage = [&](int s, int it) {
        const int k0 = it * BK;
#pragma unroll
        for (int i = 0; i < 2; ++i) {
            int q = tid + i * 256;
            int row = q >> 2, col = (q & 3) * 8;
            int tok = stok[row];
            cp16(sa + s * ASZ + (uint32_t)(row * LDA + col) * 2,
                 g_x16 + (size_t)(tok < 0 ? 0 : tok) * DDIM + k0 + col,
                 tok < 0 ? 0 : 16);
        }
        int kr = tid >> 3, col = (tid & 7) * 8;
        cp16(sb1 + s * BSZ + (uint32_t)(kr * LDB + col) * 2,
             w1p + (size_t)(k0 + kr) * FDIM + n0 + col, 16);
        cp16(sb3 + s * BSZ + (uint32_t)(kr * LDB + col) * 2,
             w3p + (size_t)(k0 + kr) * FDIM + n0 + col, 16);
        cp_commit();
    };

    const int NIT = DDIM / BK;  // 32
    load_stage(0, 0);
    load_stage(1, 1);

    for (int it = 0; it < NIT; ++it) {
        const int s = it % 3;
        if (it == NIT - 1) cp_wait<0>(); else cp_wait<1>();
        __syncthreads();
        if (it + 2 < NIT) load_stage((it + 2) % 3, it + 2);
#pragma unroll
        for (int kk = 0; kk < 2; ++kk) {
            uint32_t a[2][4], b1[2][4], b3[2][4];
#pragma unroll
            for (int im = 0; im < 2; im++)
                ldmx4(a[im], sa + s * ASZ +
                      (uint32_t)((wm * 32 + im * 16 + (lane & 15)) * LDA +
                                 kk * 16 + (lane >> 4) * 8) * 2);
#pragma unroll
            for (int j2 = 0; j2 < 2; j2++) {
                uint32_t boff = (uint32_t)((kk * 16 + (lane & 15)) * LDB +
                                           wn * 32 + j2 * 16 + (lane >> 4) * 8) * 2;
                ldmx4t(b1[j2], sb1 + s * BSZ + boff);
                ldmx4t(b3[j2], sb3 + s * BSZ + boff);
            }
#pragma unroll
            for (int im = 0; im < 2; im++)
#pragma unroll
                for (int jn = 0; jn < 4; jn++) {
                    int j2 = jn >> 1, hh = (jn & 1) * 2;
                    mma16816(acc1[im][jn], a[im], b1[j2][hh], b1[j2][hh + 1]);
                    mma16816(acc3[im][jn], a[im], b3[j2][hh], b3[j2][hh + 1]);
                }
        }
    }

    // epilogue: h = silu(acc1) * acc3 -> fp16
    const int off = g_off[e];
    const int gid = lane >> 2, tg = lane & 3;
#pragma unroll
    for (int im = 0; im < 2; im++)
#pragma unroll
        for (int jn = 0; jn < 4; jn++) {
            int fcol = n0 + wn * 32 + jn * 8 + tg * 2;
#pragma unroll
            for (int hr = 0; hr < 2; hr++) {
                int r = m0 + wm * 32 + im * 16 + gid + hr * 8;
                if (r < ne) {
                    float z1a = acc1[im][jn][hr * 2],     z1b = acc1[im][jn][hr * 2 + 1];
                    float z3a = acc3[im][jn][hr * 2],     z3b = acc3[im][jn][hr * 2 + 1];
                    float h0 = z1a / (1.f + __expf(-z1a)) * z3a;
                    float h1 = z1b / (1.f + __expf(-z1b)) * z3b;
                    *(__half2*)&g_h[(size_t)(off + r) * FDIM + fcol] =
                        __floats2half2_rn(h0, h1);
                }
            }
        }
}

// ---------------------------------------------------------------------------
// Kernel 5: grouped GEMM2 — y = h @ w2
// BM=128, BN2=128, BK=32, 3-stage, 1 sync/iter.
// 8 warps (4 M x 2 N), warp tile 32x64.
// ---------------------------------------------------------------------------
__global__ __launch_bounds__(256, 2) void gemm2_kernel() {
    const int e  = blockIdx.z;
    const int ne = g_cnt[e];
    const int m0 = blockIdx.y * BM;
    if (m0 >= ne) return;
    const int n0  = blockIdx.x * BN2;
    const int off = g_off[e];

    extern __shared__ __half sm2[];
    const uint32_t sa = smem_u32(sm2);
    const uint32_t sb = sa + SM2_B;

    const int tid = threadIdx.x, lane = tid & 31, warp = tid >> 5;
    const int wm = warp & 3, wn = warp >> 2;

    const __half* bp = g_w2h + (size_t)e * FDIM * DDIM;

    float acc[2][8][4];
#pragma unroll
    for (int i = 0; i < 2; i++)
#pragma unroll
        for (int j = 0; j < 8; j++)
#pragma unroll
            for (int q = 0; q < 4; q++) acc[i][j][q] = 0.f;

    auto load_stage = [&](int s, int it) {
        const int k0 = it * BK;
#pragma unroll
        for (int i = 0; i < 2; ++i) {
            int q = tid + i * 256;
            int row = q >> 2, col = (q & 3) * 8;
            int r = m0 + row; if (r >= ne) r = ne - 1;    // clamp (unused rows)
            cp16(sa + s * ASZ + (uint32_t)(row * LDA + col) * 2,
                 g_h + (size_t)(off + r) * FDIM + k0 + col, 16);
        }
#pragma unroll
        for (int i = 0; i < 2; ++i) {
            int q = tid + i * 256;
            int kr = q >> 4, col = (q & 15) * 8;
            cp16(sb + s * BSZ2 + (uint32_t)(kr * LDB2 + col) * 2,
                 bp + (size_t)(k0 + kr) * DDIM + n0 + col, 16);
        }
        cp_commit();
    };

    const int NIT = FDIM / BK;  // 64
    load_stage(0, 0);
    load_stage(1, 1);

    for (int it = 0; it < NIT; ++it) {
        const int s = it % 3;
        if (it == NIT - 1) cp_wait<0>(); else cp_wait<1>();
        __syncthreads();
        if (it + 2 < NIT) load_stage((it + 2) % 3, it + 2);
#pragma unroll
        for (int kk = 0; kk < 2; ++kk) {
            uint32_t a[2][4], b[4][4];
#pragma unroll
            for (int im = 0; im < 2; im++)
                ldmx4(a[im], sa + s * ASZ +
                      (uint32_t)((wm * 32 + im * 16 + (lane & 15)) * LDA +
                                 kk * 16 + (lane >> 4) * 8) * 2);
#pragma unroll
            for (int j2 = 0; j2 < 4; j2++)
                ldmx4t(b[j2], sb + s * BSZ2 +
                       (uint32_t)((kk * 16 + (lane & 15)) * LDB2 +
                                  wn * 64 + j2 * 16 + (lane >> 4) * 8) * 2);
#pragma unroll
            for (int im = 0; im < 2; im++)
#pragma unroll
                for (int jn = 0; jn < 8; jn++) {
                    int j2 = jn >> 1, hh = (jn & 1) * 2;
                    mma16816(acc[im][jn], a[im], b[j2][hh], b[j2][hh + 1]);
                }
        }
    }

    const int gid = lane >> 2, tg = lane & 3;
#pragma unroll
    for (int im = 0; im < 2; im++)
#pragma unroll
        for (int jn = 0; jn < 8; jn++) {
            int col = n0 + wn * 64 + jn * 8 + tg * 2;
#pragma unroll
            for (int hr = 0; hr < 2; hr++) {
                int r = m0 + wm * 32 + im * 16 + gid + hr * 8;
                if (r < ne) {
                    float2 v = make_float2(acc[im][jn][hr * 2], acc[im][jn][hr * 2 + 1]);
                    *(float2*)&g_y[(size_t)(off + r) * DDIM + col] = v;
                }
            }
        }
}

// ---------------------------------------------------------------------------
// Kernel 6: combine — out[t] = p0*y[slot0] + p1*y[slot1]   (deterministic)
// ---------------------------------------------------------------------------
__global__ void combine_kernel(float* __restrict__ out) {
    const int n4 = T_TOK * DDIM / 4;
    for (int i = blockIdx.x * blockDim.x + threadIdx.x; i < n4;
         i += gridDim.x * blockDim.x) {
        int t  = i >> 8;          // DDIM/4 = 256
        int c4 = i & 255;
        int e0 = g_sel[2 * t],     e1 = g_sel[2 * t + 1];
        int s0 = g_off[e0] + g_pos[2 * t];
        int s1 = g_off[e1] + g_pos[2 * t + 1];
        float p0 = g_pk[2 * t], p1 = g_pk[2 * t + 1];
        float4 v0 = ((const float4*)g_y)[s0 * 256 + c4];
        float4 v1 = ((const float4*)g_y)[s1 * 256 + c4];
        float4 o;
        o.x = p0 * v0.x + p1 * v1.x;
        o.y = p0 * v0.y + p1 * v1.y;
        o.z = p0 * v0.z + p1 * v1.z;
        o.w = p0 * v0.w + p1 * v1.w;
        ((float4*)out)[i] = o;
    }
}

// ---------------------------------------------------------------------------
// Launcher
// ---------------------------------------------------------------------------
extern "C" void kernel_launch(void* const* d_in, const int* in_sizes, int n_in,
                              void* d_out, int out_size) {
    const float* x  = (const float*)d_in[0];
    const float* wg = (const float*)d_in[1];
    const float* w1 = (const float*)d_in[2];
    const float* w3 = (const float*)d_in[3];
    const float* w2 = (const float*)d_in[4];
    float* out = (float*)d_out;

    cudaFuncSetAttribute(gemm1_kernel, cudaFuncAttributeMaxDynamicSharedMemorySize, SMEM1);
    cudaFuncSetAttribute(gemm2_kernel, cudaFuncAttributeMaxDynamicSharedMemorySize, SMEM2);

    zero_cnt_kernel<<<1, 32>>>();
    convert_kernel<<<4096, 256>>>(w1, w3, w2);
    gate_kernel<<<T_TOK / 8, 256>>>(x, wg);
    offsets_kernel<<<1, 32>>>();
    gemm1_kernel<<<dim3(FDIM / BN,  T_TOK / BM, NEXP), 256, SMEM1>>>();
    gemm2_kernel<<<dim3(DDIM / BN2, T_TOK / BM, NEXP), 256, SMEM2>>>();
    combine_kernel<<<4096, 256>>>(out);
}

// round 12
// speedup vs baseline: 1.2725x; 1.2725x over previous
#include <cuda_runtime.h>
#include <cuda_fp16.h>
#include <cstdint>

// Problem constants
#define T_TOK 8192
#define DDIM  1024
#define NEXP  8
#define FDIM  2048

// GEMM tiling (R0 proven configuration)
#define BM 128
#define BN 64
#define BK 32
#define LDA 40   // padded A smem stride (halves) -> conflict-free ldmatrix
#define LDB 72   // padded B smem stride (halves)

// ---------------------------------------------------------------------------
// Scratch (device globals). g_h / g_y are per-expert strided: slot s of
// expert e lives at row (e*T_TOK + s). No offsets/prefix-sum needed anywhere.
// ---------------------------------------------------------------------------
__device__ __half g_x16[(size_t)T_TOK * DDIM];
__device__ __half g_w1h[(size_t)NEXP * DDIM * FDIM];
__device__ __half g_w3h[(size_t)NEXP * DDIM * FDIM];
__device__ __half g_w2h[(size_t)NEXP * FDIM * DDIM];
__device__ __half g_h  [(size_t)NEXP * T_TOK * FDIM];   // 256 MB
__device__ float  g_y  [(size_t)NEXP * T_TOK * DDIM];   // 256 MB
__device__ int    g_tok[NEXP * T_TOK];                  // per-expert slot -> token
__device__ int    g_cnt[NEXP];
__device__ int    g_sel[T_TOK * 2];
__device__ int    g_pos[T_TOK * 2];
__device__ float  g_pk [T_TOK * 2];

// ---------------------------------------------------------------------------
// PTX helpers
// ---------------------------------------------------------------------------
__device__ __forceinline__ void cp16(uint32_t dst, const void* src, int srcsize) {
    asm volatile("cp.async.cg.shared.global [%0], [%1], 16, %2;\n"
                 :: "r"(dst), "l"(src), "r"(srcsize));
}
__device__ __forceinline__ void cp_commit() {
    asm volatile("cp.async.commit_group;\n");
}
template <int N>
__device__ __forceinline__ void cp_wait() {
    asm volatile("cp.async.wait_group %0;\n" :: "n"(N));
}
__device__ __forceinline__ void ldmx4(uint32_t* r, uint32_t addr) {
    asm volatile("ldmatrix.sync.aligned.m8n8.x4.shared.b16 {%0,%1,%2,%3}, [%4];\n"
                 : "=r"(r[0]), "=r"(r[1]), "=r"(r[2]), "=r"(r[3]) : "r"(addr));
}
__device__ __forceinline__ void ldmx4t(uint32_t* r, uint32_t addr) {
    asm volatile("ldmatrix.sync.aligned.m8n8.x4.trans.shared.b16 {%0,%1,%2,%3}, [%4];\n"
                 : "=r"(r[0]), "=r"(r[1]), "=r"(r[2]), "=r"(r[3]) : "r"(addr));
}
__device__ __forceinline__ void mma16816(float* c, const uint32_t* a, uint32_t b0, uint32_t b1) {
    asm volatile(
        "mma.sync.aligned.m16n8k16.row.col.f32.f16.f16.f32 "
        "{%0,%1,%2,%3}, {%4,%5,%6,%7}, {%8,%9}, {%0,%1,%2,%3};\n"
        : "+f"(c[0]), "+f"(c[1]), "+f"(c[2]), "+f"(c[3])
        : "r"(a[0]), "r"(a[1]), "r"(a[2]), "r"(a[3]), "r"(b0), "r"(b1));
}

// ---------------------------------------------------------------------------
// Kernel 1: fp32 -> fp16 conversion of w1, w3, w2 + zero routing counters
// ---------------------------------------------------------------------------
__global__ void convert_kernel(const float* __restrict__ w1,
                               const float* __restrict__ w3,
                               const float* __restrict__ w2) {
    if (blockIdx.x == 0 && threadIdx.x < NEXP) g_cnt[threadIdx.x] = 0;
    const int n4w = NEXP * DDIM * FDIM / 4;
    for (int i = blockIdx.x * blockDim.x + threadIdx.x; i < n4w;
         i += gridDim.x * blockDim.x) {
        float4 a;
        a = ((const float4*)w1)[i];
        ((__half2*)g_w1h)[2 * i]     = __floats2half2_rn(a.x, a.y);
        ((__half2*)g_w1h)[2 * i + 1] = __floats2half2_rn(a.z, a.w);
        a = ((const float4*)w3)[i];
        ((__half2*)g_w3h)[2 * i]     = __floats2half2_rn(a.x, a.y);
        ((__half2*)g_w3h)[2 * i + 1] = __floats2half2_rn(a.z, a.w);
        a = ((const float4*)w2)[i];
        ((__half2*)g_w2h)[2 * i]     = __floats2half2_rn(a.x, a.y);
        ((__half2*)g_w2h)[2 * i + 1] = __floats2half2_rn(a.z, a.w);
    }
}

// ---------------------------------------------------------------------------
// Kernel 2: gating (exact fp32) + routing + x -> fp16. One warp per token.
// ---------------------------------------------------------------------------
__global__ void gate_kernel(const float* __restrict__ x, const float* __restrict__ wg) {
    int t = blockIdx.x * 8 + (threadIdx.x >> 5);
    int lane = threadIdx.x & 31;
    const float* xr = x + (size_t)t * DDIM;
    float acc[NEXP];
#pragma unroll
    for (int e = 0; e < NEXP; e++) acc[e] = 0.f;
    for (int d = lane; d < DDIM; d += 32) {
        float xv = xr[d];
        g_x16[(size_t)t * DDIM + d] = __float2half(xv);
        const float* wr = wg + d * NEXP;
#pragma unroll
        for (int e = 0; e < NEXP; e++) acc[e] += xv * wr[e];
    }
#pragma unroll
    for (int e = 0; e < NEXP; e++) {
#pragma unroll
        for (int o = 16; o; o >>= 1)
            acc[e] += __shfl_xor_sync(0xffffffffu, acc[e], o);
    }
    if (lane == 0) {
        int e0 = 0; float b0 = acc[0];
#pragma unroll
        for (int e = 1; e < NEXP; e++)
            if (acc[e] > b0) { b0 = acc[e]; e0 = e; }   // strict >: lowest index on tie
        int e1 = -1; float b1 = -1e30f;
#pragma unroll
        for (int e = 0; e < NEXP; e++)
            if (e != e0 && acc[e] > b1) { b1 = acc[e]; e1 = e; }
        float ex  = expf(b1 - b0);
        float inv = 1.f / (1.f + ex);
        int pos0 = atomicAdd(&g_cnt[e0], 1);
        int pos1 = atomicAdd(&g_cnt[e1], 1);
        g_tok[e0 * T_TOK + pos0] = t;
        g_tok[e1 * T_TOK + pos1] = t;
        g_sel[2 * t] = e0;   g_sel[2 * t + 1] = e1;
        g_pos[2 * t] = pos0; g_pos[2 * t + 1] = pos1;
        g_pk [2 * t] = inv;  g_pk [2 * t + 1] = ex * inv;
    }
}

// ---------------------------------------------------------------------------
// Kernel 3: grouped GEMM1 — h = silu(x@w1) * (x@w3), gathered rows.
// R0-proven structure: 2-stage cp.async, 2 syncs/iter, 8 warps (4M x 2N),
// warp tile 32x32 per matrix.
// ---------------------------------------------------------------------------
__global__ __launch_bounds__(256, 2) void gemm1_kernel() {
    const int e  = blockIdx.z;
    const int ne = g_cnt[e];
    const int m0 = blockIdx.y * BM;
    if (m0 >= ne) return;
    const int n0 = blockIdx.x * BN;

    __shared__ int    stok[BM];
    __shared__ __half sA [2][BM][LDA];
    __shared__ __half sB1[2][BK][LDB];
    __shared__ __half sB3[2][BK][LDB];

    const int tid = threadIdx.x, lane = tid & 31, warp = tid >> 5;
    const int wm = warp & 3, wn = warp >> 2;

    if (tid < BM) {
        int r = m0 + tid;
        stok[tid] = (r < ne) ? g_tok[e * T_TOK + r] : -1;
    }
    __syncthreads();

    const __half* w1p = g_w1h + (size_t)e * DDIM * FDIM;
    const __half* w3p = g_w3h + (size_t)e * DDIM * FDIM;

    const uint32_t sa  = (uint32_t)__cvta_generic_to_shared(&sA [0][0][0]);
    const uint32_t sb1 = (uint32_t)__cvta_generic_to_shared(&sB1[0][0][0]);
    const uint32_t sb3 = (uint32_t)__cvta_generic_to_shared(&sB3[0][0][0]);
    const uint32_t ASZ = BM * LDA * 2, BSZ = BK * LDB * 2;

    float acc1[2][4][4], acc3[2][4][4];
#pragma unroll
    for (int i = 0; i < 2; i++)
#pragma unroll
        for (int j = 0; j < 4; j++)
#pragma unroll
            for (int q = 0; q < 4; q++) { acc1[i][j][q] = 0.f; acc3[i][j][q] = 0.f; }

    auto load_stage = [&](int s, int k0) {
#pragma unroll
        for (int it = 0; it < 2; ++it) {
            int c = tid + it * 256;
            int row = c >> 2, col = (c & 3) * 8;
            int tok = stok[row];
            uint32_t d = sa + s * ASZ + (uint32_t)(row * LDA + col) * 2;
            const __half* src = g_x16 + (size_t)(tok < 0 ? 0 : tok) * DDIM + k0 + col;
            cp16(d, src, tok < 0 ? 0 : 16);
        }
        int kr = tid >> 3, col = (tid & 7) * 8;
        cp16(sb1 + s * BSZ + (uint32_t)(kr * LDB + col) * 2,
             w1p + (size_t)(k0 + kr) * FDIM + n0 + col, 16);
        cp16(sb3 + s * BSZ + (uint32_t)(kr * LDB + col) * 2,
             w3p + (size_t)(k0 + kr) * FDIM + n0 + col, 16);
    };

    const int NIT = DDIM / BK;  // 32
    load_stage(0, 0);
    cp_commit();

    for (int it = 0; it < NIT; ++it) {
        int s = it & 1;
        if (it + 1 < NIT) {
            load_stage(s ^ 1, (it + 1) * BK);
            cp_commit();
            cp_wait<1>();
        } else {
            cp_wait<0>();
        }
        __syncthreads();
#pragma unroll
        for (int kk = 0; kk < 2; ++kk) {
            uint32_t a[2][4], b1[2][4], b3[2][4];
#pragma unroll
            for (int im = 0; im < 2; im++)
                ldmx4(a[im], sa + s * ASZ +
                      (uint32_t)((wm * 32 + im * 16 + (lane & 15)) * LDA +
                                 kk * 16 + (lane >> 4) * 8) * 2);
#pragma unroll
            for (int j2 = 0; j2 < 2; j2++) {
                uint32_t boff = (uint32_t)((kk * 16 + (lane & 15)) * LDB +
                                           wn * 32 + j2 * 16 + (lane >> 4) * 8) * 2;
                ldmx4t(b1[j2], sb1 + s * BSZ + boff);
                ldmx4t(b3[j2], sb3 + s * BSZ + boff);
            }
#pragma unroll
            for (int im = 0; im < 2; im++)
#pragma unroll
                for (int jn = 0; jn < 4; jn++) {
                    int j2 = jn >> 1, hh = (jn & 1) * 2;
                    mma16816(acc1[im][jn], a[im], b1[j2][hh], b1[j2][hh + 1]);
                    mma16816(acc3[im][jn], a[im], b3[j2][hh], b3[j2][hh + 1]);
                }
        }
        __syncthreads();
    }

    // epilogue: h = silu(acc1) * acc3 -> fp16 ; per-expert strided rows
    const int gid = lane >> 2, tg = lane & 3;
#pragma unroll
    for (int im = 0; im < 2; im++)
#pragma unroll
        for (int jn = 0; jn < 4; jn++) {
            int fcol = n0 + wn * 32 + jn * 8 + tg * 2;
#pragma unroll
            for (int hr = 0; hr < 2; hr++) {
                int r = m0 + wm * 32 + im * 16 + gid + hr * 8;
                if (r < ne) {
                    float z1a = acc1[im][jn][hr * 2],     z1b = acc1[im][jn][hr * 2 + 1];
                    float z3a = acc3[im][jn][hr * 2],     z3b = acc3[im][jn][hr * 2 + 1];
                    float h0 = z1a / (1.f + __expf(-z1a)) * z3a;
                    float h1 = z1b / (1.f + __expf(-z1b)) * z3b;
                    *(__half2*)&g_h[(size_t)(e * T_TOK + r) * FDIM + fcol] =
                        __floats2half2_rn(h0, h1);
                }
            }
        }
}

// ---------------------------------------------------------------------------
// Kernel 4: grouped GEMM2 — y = h @ w2  (R0-proven structure)
// ---------------------------------------------------------------------------
__global__ __launch_bounds__(256, 2) void gemm2_kernel() {
    const int e  = blockIdx.z;
    const int ne = g_cnt[e];
    const int m0 = blockIdx.y * BM;
    if (m0 >= ne) return;
    const int n0 = blockIdx.x * BN;

    __shared__ __half sA[2][BM][LDA];
    __shared__ __half sB[2][BK][LDB];

    const int tid = threadIdx.x, lane = tid & 31, warp = tid >> 5;
    const int wm = warp & 3, wn = warp >> 2;

    const __half* bp = g_w2h + (size_t)e * FDIM * DDIM;

    const uint32_t sa = (uint32_t)__cvta_generic_to_shared(&sA[0][0][0]);
    const uint32_t sb = (uint32_t)__cvta_generic_to_shared(&sB[0][0][0]);
    const uint32_t ASZ = BM * LDA * 2, BSZ = BK * LDB * 2;

    float acc[2][4][4];
#pragma unroll
    for (int i = 0; i < 2; i++)
#pragma unroll
        for (int j = 0; j < 4; j++)
#pragma unroll
            for (int q = 0; q < 4; q++) acc[i][j][q] = 0.f;

    auto load_stage = [&](int s, int k0) {
#pragma unroll
        for (int it = 0; it < 2; ++it) {
            int c = tid + it * 256;
            int row = c >> 2, col = (c & 3) * 8;
            int r = m0 + row; if (r >= ne) r = ne - 1;     // clamp (rows >= ne unused)
            uint32_t d = sa + s * ASZ + (uint32_t)(row * LDA + col) * 2;
            cp16(d, g_h + (size_t)(e * T_TOK + r) * FDIM + k0 + col, 16);
        }
        int kr = tid >> 3, col = (tid & 7) * 8;
        cp16(sb + s * BSZ + (uint32_t)(kr * LDB + col) * 2,
             bp + (size_t)(k0 + kr) * DDIM + n0 + col, 16);
    };

    const int NIT = FDIM / BK;  // 64
    load_stage(0, 0);
    cp_commit();

    for (int it = 0; it < NIT; ++it) {
        int s = it & 1;
        if (it + 1 < NIT) {
            load_stage(s ^ 1, (it + 1) * BK);
            cp_commit();
            cp_wait<1>();
        } else {
            cp_wait<0>();
        }
        __syncthreads();
#pragma unroll
        for (int kk = 0; kk < 2; ++kk) {
            uint32_t a[2][4], b[2][4];
#pragma unroll
            for (int im = 0; im < 2; im++)
                ldmx4(a[im], sa + s * ASZ +
                      (uint32_t)((wm * 32 + im * 16 + (lane & 15)) * LDA +
                                 kk * 16 + (lane >> 4) * 8) * 2);
#pragma unroll
            for (int j2 = 0; j2 < 2; j2++)
                ldmx4t(b[j2], sb + s * BSZ +
                       (uint32_t)((kk * 16 + (lane & 15)) * LDB +
                                  wn * 32 + j2 * 16 + (lane >> 4) * 8) * 2);
#pragma unroll
            for (int im = 0; im < 2; im++)
#pragma unroll
                for (int jn = 0; jn < 4; jn++) {
                    int j2 = jn >> 1, hh = (jn & 1) * 2;
                    mma16816(acc[im][jn], a[im], b[j2][hh], b[j2][hh + 1]);
                }
        }
        __syncthreads();
    }

    const int gid = lane >> 2, tg = lane & 3;
#pragma unroll
    for (int im = 0; im < 2; im++)
#pragma unroll
        for (int jn = 0; jn < 4; jn++) {
            int col = n0 + wn * 32 + jn * 8 + tg * 2;
#pragma unroll
            for (int hr = 0; hr < 2; hr++) {
                int r = m0 + wm * 32 + im * 16 + gid + hr * 8;
                if (r < ne) {
                    float2 v = make_float2(acc[im][jn][hr * 2], acc[im][jn][hr * 2 + 1]);
                    *(float2*)&g_y[(size_t)(e * T_TOK + r) * DDIM + col] = v;
                }
            }
        }
}

// ---------------------------------------------------------------------------
// Kernel 5: combine — out[t] = p0*y[e0, pos0] + p1*y[e1, pos1] (deterministic)
// ---------------------------------------------------------------------------
__global__ void combine_kernel(float* __restrict__ out) {
    const int n4 = T_TOK * DDIM / 4;
    for (int i = blockIdx.x * blockDim.x + threadIdx.x; i < n4;
         i += gridDim.x * blockDim.x) {
        int t  = i >> 8;          // DDIM/4 = 256
        int c4 = i & 255;
        int s0 = g_sel[2 * t]     * T_TOK + g_pos[2 * t];
        int s1 = g_sel[2 * t + 1] * T_TOK + g_pos[2 * t + 1];
        float p0 = g_pk[2 * t], p1 = g_pk[2 * t + 1];
        float4 v0 = ((const float4*)g_y)[(size_t)s0 * 256 + c4];
        float4 v1 = ((const float4*)g_y)[(size_t)s1 * 256 + c4];
        float4 o;
        o.x = p0 * v0.x + p1 * v1.x;
        o.y = p0 * v0.y + p1 * v1.y;
        o.z = p0 * v0.z + p1 * v1.z;
        o.w = p0 * v0.w + p1 * v1.w;
        ((float4*)out)[i] = o;
    }
}

// ---------------------------------------------------------------------------
// Launcher — 5 kernels
// ---------------------------------------------------------------------------
extern "C" void kernel_launch(void* const* d_in, const int* in_sizes, int n_in,
                              void* d_out, int out_size) {
    const float* x  = (const float*)d_in[0];
    const float* wg = (const float*)d_in[1];
    const float* w1 = (const float*)d_in[2];
    const float* w3 = (const float*)d_in[3];
    const float* w2 = (const float*)d_in[4];
    float* out = (float*)d_out;

    convert_kernel<<<4096, 256>>>(w1, w3, w2);
    gate_kernel<<<T_TOK / 8, 256>>>(x, wg);
    gemm1_kernel<<<dim3(FDIM / BN, T_TOK / BM, NEXP), 256>>>();
    gemm2_kernel<<<dim3(DDIM / BN, T_TOK / BM, NEXP), 256>>>();
    combine_kernel<<<4096, 256>>>(out);
}